// round 6
// baseline (speedup 1.0000x reference)
#include <cuda_runtime.h>
#include <cstdint>
#include <math.h>

#define S_LEN  2048
#define G_GRP  2
#define EMB    1024
#define NH     16
#define NKV    4
#define HD     64
#define MROWS  (S_LEN * G_GRP)      // 4096
#define KVW    (NKV * HD)           // 256
#define ROWQ   (G_GRP * EMB)        // 2048
#define ROWK   (G_GRP * KVW)        // 512

// ---------------- scratch ----------------
// All k-contraction dimensions are stored with the in-group address permutation
// addr(q) = 2*(q&3) + (q>>2) applied within every aligned 8-element group.
__device__ float g_X[MROWS * EMB];              // permuted along EMB
__device__ float g_Q[MROWS * EMB];              // permuted along head dim d
__device__ float g_K[MROWS * KVW];              // permuted along head dim d
__device__ float g_V[MROWS * KVW];              // TRUE layout (perm applied at smem staging)
__device__ float g_O[MROWS * EMB];              // permuted along EMB
__device__ float g_WT[(EMB + 2 * KVW) * EMB];   // permuted along EMB (k)
__device__ float g_WoT[EMB * EMB];              // permuted along EMB (k)

// ================= helpers =================
__device__ __forceinline__ uint32_t smem_u32(const void* p) {
    uint32_t a;
    asm("{ .reg .u64 t; cvta.to.shared.u64 t, %1; cvt.u32.u64 %0, t; }" : "=r"(a) : "l"(p));
    return a;
}
__device__ __forceinline__ uint32_t f2tf32(float x) {
    uint32_t r;
    asm("cvt.rna.tf32.f32 %0, %1;" : "=r"(r) : "f"(x));
    return r;
}
__device__ __forceinline__ float rtf(float x) { return __uint_as_float(f2tf32(x)); }

__device__ __forceinline__ void mma_tf32(float c[4], const uint32_t a[4], const uint32_t b[2]) {
    asm volatile(
        "mma.sync.aligned.m16n8k8.row.col.f32.tf32.tf32.f32 "
        "{%0,%1,%2,%3}, {%4,%5,%6,%7}, {%8,%9}, {%0,%1,%2,%3};"
        : "+f"(c[0]), "+f"(c[1]), "+f"(c[2]), "+f"(c[3])
        : "r"(a[0]), "r"(a[1]), "r"(a[2]), "r"(a[3]), "r"(b[0]), "r"(b[1]));
}

__device__ __forceinline__ void cpa16(uint32_t dst, const float* src) {
    asm volatile("cp.async.cg.shared.global [%0], [%1], 16;" :: "r"(dst), "l"(src));
}
__device__ __forceinline__ void cpa_commit() { asm volatile("cp.async.commit_group;"); }
template <int N>
__device__ __forceinline__ void cpa_wait() { asm volatile("cp.async.wait_group %0;" :: "n"(N)); }

// ================= producer-side prep =================
// WT permuted along k (EMB) within 8-groups.
__global__ __launch_bounds__(1024) void transpose_all(
    const float* __restrict__ Wq, const float* __restrict__ Wk,
    const float* __restrict__ Wv, const float* __restrict__ Wo)
{
    __shared__ float t[32][33];
    const int bx = blockIdx.x;
    const float* W; float* WT; int N; int nb;
    if (bx < 32)      { W = Wq; WT = g_WT;                               N = EMB; nb = bx; }
    else if (bx < 40) { W = Wk; WT = g_WT + (size_t)EMB * EMB;           N = KVW; nb = bx - 32; }
    else if (bx < 48) { W = Wv; WT = g_WT + (size_t)(EMB + KVW) * EMB;   N = KVW; nb = bx - 40; }
    else              { W = Wo; WT = g_WoT;                              N = EMB; nb = bx - 48; }

    int n = nb * 32 + threadIdx.x;
    int k = blockIdx.y * 32 + threadIdx.y;
    t[threadIdx.y][threadIdx.x] = rtf(W[(size_t)k * N + n]);
    __syncthreads();
    int n2 = nb * 32 + threadIdx.y;
    int k2 = blockIdx.y * 32 + threadIdx.x;
    int k2p = (k2 & ~7) | (2 * (k2 & 3) + ((k2 >> 2) & 1));
    WT[(size_t)n2 * EMB + k2p] = t[threadIdx.x][threadIdx.y];
}

// round + permute X along EMB: out positions (0..7) <- in (0,4,1,5,2,6,3,7)
__global__ __launch_bounds__(512) void round_x(const float* __restrict__ x) {
    int i = blockIdx.x * 512 + threadIdx.x;       // 8 floats per thread
    const float4* src = reinterpret_cast<const float4*>(x) + 2 * (size_t)i;
    float4 v0 = src[0], v1 = src[1];
    float4 o0 = make_float4(rtf(v0.x), rtf(v1.x), rtf(v0.y), rtf(v1.y));
    float4 o1 = make_float4(rtf(v0.z), rtf(v1.z), rtf(v0.w), rtf(v1.w));
    float4* dst = reinterpret_cast<float4*>(g_X) + 2 * (size_t)i;
    dst[0] = o0; dst[1] = o1;
}

// ================= tf32 mma GEMM: 128x128 CTA tile, 64x64 warp tile ==========
#define AST 40
#define ABUF (128 * AST)
#define GEMM_SMEM (4 * ABUF * 4)     // 81920 B

template <bool ROUND, bool PERM>
__device__ __forceinline__ void gemm_tile(
    const float* __restrict__ A, const float* __restrict__ BT,
    float* __restrict__ C, int ldc, int m0, int n0bt, int c0)
{
    extern __shared__ uint32_t dsm[];
    const uint32_t sb = smem_u32(dsm);

    const int tid  = threadIdx.x;      // 0..127
    const int lane = tid & 31;
    const int wid  = tid >> 5;
    const int wm   = wid >> 1;
    const int wn   = wid & 1;
    const int g    = lane >> 2;
    const int tg   = lane & 3;

    float acc[4][8][4];
#pragma unroll
    for (int mi = 0; mi < 4; mi++)
#pragma unroll
        for (int nt = 0; nt < 8; nt++)
#pragma unroll
            for (int j = 0; j < 4; j++) acc[mi][nt][j] = 0.0f;

    const int row = tid >> 3;          // 0..15
    const int q   = (tid & 7) * 4;

    auto stage = [&](int c, int buf) {
        const int k0 = c * 32;
        const uint32_t aBase = sb + (uint32_t)(2 * buf) * ABUF * 4;
        const uint32_t bBase = aBase + ABUF * 4;
#pragma unroll
        for (int t = 0; t < 8; t++) {
            int r = row + t * 16;
            cpa16(aBase + (uint32_t)(r * AST + q) * 4, &A [(size_t)(m0 + r) * EMB + k0 + q]);
            cpa16(bBase + (uint32_t)(r * AST + q) * 4, &BT[(size_t)(n0bt + r) * EMB + k0 + q]);
        }
    };

    stage(0, 0);
    cpa_commit();

    for (int c = 0; c < 32; c++) {
        if (c < 31) {
            stage(c + 1, (c + 1) & 1);
            cpa_commit();
            cpa_wait<1>();
        } else {
            cpa_wait<0>();
        }
        __syncthreads();

        const uint32_t* sA = dsm + (size_t)(2 * (c & 1)) * ABUF;
        const uint32_t* sB = sA + ABUF;
#pragma unroll
        for (int kc = 0; kc < 4; kc++) {
            const int kk = kc * 8;
            uint32_t a[4][4];
#pragma unroll
            for (int mi = 0; mi < 4; mi++) {
                int r = wm * 64 + mi * 16;
                uint2 t0 = *reinterpret_cast<const uint2*>(&sA[(r + g) * AST + kk + 2 * tg]);
                uint2 t1 = *reinterpret_cast<const uint2*>(&sA[(r + g + 8) * AST + kk + 2 * tg]);
                a[mi][0] = t0.x; a[mi][2] = t0.y;
                a[mi][1] = t1.x; a[mi][3] = t1.y;
            }
#pragma unroll
            for (int nt = 0; nt < 8; nt++) {
                int n = wn * 64 + nt * 8;
                uint2 tb = *reinterpret_cast<const uint2*>(&sB[(n + g) * AST + kk + 2 * tg]);
                uint32_t b[2] = {tb.x, tb.y};
                mma_tf32(acc[0][nt], a[0], b);
                mma_tf32(acc[1][nt], a[1], b);
                mma_tf32(acc[2][nt], a[2], b);
                mma_tf32(acc[3][nt], a[3], b);
            }
        }
        __syncthreads();
    }

    // epilogue
    const int pa0 = ((2 * tg) & 3) * 2 + (tg >> 1);        // addr(2tg)
    const int pa1 = ((2 * tg + 1) & 3) * 2 + (tg >> 1);    // addr(2tg+1)
#pragma unroll
    for (int mi = 0; mi < 4; mi++) {
        int r0 = m0 + wm * 64 + mi * 16 + g;
#pragma unroll
        for (int nt = 0; nt < 8; nt++) {
            int colg = c0 + wn * 64 + nt * 8;
            if (PERM) {
                C[(size_t)r0 * ldc + colg + pa0]       = rtf(acc[mi][nt][0]);
                C[(size_t)r0 * ldc + colg + pa1]       = rtf(acc[mi][nt][1]);
                C[(size_t)(r0 + 8) * ldc + colg + pa0] = rtf(acc[mi][nt][2]);
                C[(size_t)(r0 + 8) * ldc + colg + pa1] = rtf(acc[mi][nt][3]);
            } else {
                int col = colg + 2 * tg;
                float2 v0, v1;
                if (ROUND) {
                    v0 = make_float2(rtf(acc[mi][nt][0]), rtf(acc[mi][nt][1]));
                    v1 = make_float2(rtf(acc[mi][nt][2]), rtf(acc[mi][nt][3]));
                } else {
                    v0 = make_float2(acc[mi][nt][0], acc[mi][nt][1]);
                    v1 = make_float2(acc[mi][nt][2], acc[mi][nt][3]);
                }
                *reinterpret_cast<float2*>(&C[(size_t)r0 * ldc + col])       = v0;
                *reinterpret_cast<float2*>(&C[(size_t)(r0 + 8) * ldc + col]) = v1;
            }
        }
    }
}

__global__ __launch_bounds__(128) void qkv_mma() {
    int nb = blockIdx.x;
    int m0 = blockIdx.y * 128;
    if (nb < 8)
        gemm_tile<true, true >(g_X, g_WT, g_Q, EMB, m0, nb * 128, nb * 128);
    else if (nb < 10)
        gemm_tile<true, true >(g_X, g_WT, g_K, KVW, m0, nb * 128, (nb - 8) * 128);
    else
        gemm_tile<true, false>(g_X, g_WT, g_V, KVW, m0, nb * 128, (nb - 10) * 128);
}

__global__ __launch_bounds__(128) void oproj_mma(float* __restrict__ out) {
    gemm_tile<false, false>(g_O, g_WoT, out, EMB, blockIdx.y * 128, blockIdx.x * 128, blockIdx.x * 128);
}

// ================= flash attention: BM=128, 4 warps x 32 rows ================
#define QST  72                       // Q/P stride (72 % 32 == 8)
#define KSTK 72                       // K stride
#define KSTV 68                       // V stride (68 % 32 == 4)
#define PS_SZ (128 * QST)             // 9216 floats
#define KBUF  (64 * KSTK)             // 4608
#define VBUF  (64 * KSTV)             // 4352
#define FA_SMEM ((PS_SZ + 2 * KBUF + 2 * VBUF) * 4)   // 108544 B

__global__ __launch_bounds__(128) void flash_mma()
{
    extern __shared__ float fsm[];
    float* Ps = fsm;                                   // [128][QST] (Q staging, then P)
    float* Kb0 = fsm + PS_SZ;
    float* Kb1 = Kb0 + KBUF;
    float* Vb0 = Kb1 + KBUF;
    float* Vb1 = Vb0 + VBUF;
    const uint32_t sb = smem_u32(fsm);

    const int tid  = threadIdx.x;
    const int lane = tid & 31;
    const int w    = tid >> 5;
    const int g    = lane >> 2;
    const int tg   = lane & 3;
    const int wr   = w * 32;

    const int gh  = blockIdx.x;
    const int qb  = (int)gridDim.y - 1 - blockIdx.y;
    const int grp = gh & 1;
    const int h   = gh >> 1;
    const int kvh = h >> 2;

    const float* Qp = g_Q + grp * EMB + h * HD;
    const float* Kp = g_K + grp * KVW + kvh * HD;
    const float* Vp = g_V + grp * KVW + kvh * HD;
    float*       Op = g_O + grp * EMB + h * HD;

    const int q0 = qb * 128;
    const float SC = 0.125f * 1.4426950408889634f;   // (1/sqrt(64)) * log2(e)

    // ---- stage Q * SC (tf32-rounded) ----
    {
        const int row = tid >> 4;
        const int c   = (tid & 15) * 4;
#pragma unroll
        for (int p = 0; p < 16; p++) {
            int r = row + p * 8;
            float4 qv = *reinterpret_cast<const float4*>(&Qp[(size_t)(q0 + r) * ROWQ + c]);
            float* d = &Ps[r * QST + c];
            d[0] = rtf(qv.x * SC); d[1] = rtf(qv.y * SC);
            d[2] = rtf(qv.z * SC); d[3] = rtf(qv.w * SC);
        }
    }
    __syncthreads();

    // ---- hoist Q fragments (vectorized, permuted layout) ----
    uint32_t aq[2][8][4];
    const uint32_t* Pu = reinterpret_cast<const uint32_t*>(Ps);
#pragma unroll
    for (int mi = 0; mi < 2; mi++) {
        const int base = wr + mi * 16;
#pragma unroll
        for (int kc = 0; kc < 8; kc++) {
            const int kk = kc * 8;
            uint2 t0 = *reinterpret_cast<const uint2*>(&Pu[(base + g) * QST + kk + 2 * tg]);
            uint2 t1 = *reinterpret_cast<const uint2*>(&Pu[(base + g + 8) * QST + kk + 2 * tg]);
            aq[mi][kc][0] = t0.x; aq[mi][kc][2] = t0.y;
            aq[mi][kc][1] = t1.x; aq[mi][kc][3] = t1.y;
        }
    }
    __syncthreads();

    // ---- K/V staging (V rows placed at permuted addresses) ----
    const int srow  = tid >> 4;                                  // 0..7
    const int srowV = 2 * (srow & 3) + (srow >> 2);              // addr(srow)
    const int sq    = (tid & 15) * 4;
    auto stage_kv = [&](int kb, int buf) {
        const int kn = kb * 64;
        const uint32_t kBase = sb + (uint32_t)(PS_SZ + buf * KBUF) * 4;
        const uint32_t vBase = sb + (uint32_t)(PS_SZ + 2 * KBUF + buf * VBUF) * 4;
#pragma unroll
        for (int p = 0; p < 8; p++) {
            int r = srow + p * 8;
            cpa16(kBase + (uint32_t)(r * KSTK + sq) * 4, &Kp[(size_t)(kn + r) * ROWK + sq]);
            cpa16(vBase + (uint32_t)((srowV + p * 8) * KSTV + sq) * 4,
                  &Vp[(size_t)(kn + r) * ROWK + sq]);
        }
    };

    float m_i[2][2] = {{-1e30f, -1e30f}, {-1e30f, -1e30f}};
    float l_i[2][2] = {{0.0f, 0.0f}, {0.0f, 0.0f}};
    float o[2][8][4];
#pragma unroll
    for (int mi = 0; mi < 2; mi++)
#pragma unroll
        for (int nt = 0; nt < 8; nt++)
#pragma unroll
            for (int j = 0; j < 4; j++) o[mi][nt][j] = 0.0f;

    const int kbmax = 2 * qb + 1;
    stage_kv(0, 0);
    cpa_commit();

    const int pa0 = ((2 * tg) & 3) * 2 + (tg >> 1);        // addr(2tg)
    const int pa1 = ((2 * tg + 1) & 3) * 2 + (tg >> 1);    // addr(2tg+1)

    for (int kb = 0; kb <= kbmax; kb++) {
        const int kn  = kb * 64;
        const int buf = kb & 1;
        if (kb < kbmax) {
            stage_kv(kb + 1, buf ^ 1);
            cpa_commit();
            cpa_wait<1>();
        } else {
            cpa_wait<0>();
        }
        __syncthreads();

        const uint32_t* Ks = reinterpret_cast<const uint32_t*>(buf ? Kb1 : Kb0);
        const uint32_t* Vs = reinterpret_cast<const uint32_t*>(buf ? Vb1 : Vb0);

        // ---- S = (Q*SC) K^T ----
        float s[2][8][4];
#pragma unroll
        for (int mi = 0; mi < 2; mi++)
#pragma unroll
            for (int nt = 0; nt < 8; nt++)
#pragma unroll
                for (int j = 0; j < 4; j++) s[mi][nt][j] = 0.0f;

#pragma unroll
        for (int kc = 0; kc < 8; kc++) {
            const int kk = kc * 8;
#pragma unroll
            for (int nt = 0; nt < 8; nt++) {
                uint2 tb = *reinterpret_cast<const uint2*>(&Ks[(nt * 8 + g) * KSTK + kk + 2 * tg]);
                uint32_t b[2] = {tb.x, tb.y};
                mma_tf32(s[0][nt], aq[0][kc], b);
                mma_tf32(s[1][nt], aq[1][kc], b);
            }
        }

        // ---- online softmax (base-2 domain) ----
        const bool diag = (kn + 63 > q0);
#pragma unroll
        for (int mi = 0; mi < 2; mi++) {
            const int r0 = q0 + wr + mi * 16 + g;
            const int r1 = r0 + 8;
            float mx0 = -1e30f, mx1 = -1e30f;
#pragma unroll
            for (int nt = 0; nt < 8; nt++) {
                int cc = kn + nt * 8 + 2 * tg;
                float v0 = s[mi][nt][0], v1 = s[mi][nt][1];
                float v2 = s[mi][nt][2], v3 = s[mi][nt][3];
                if (diag) {
                    if (cc > r0)     v0 = -1e30f;
                    if (cc + 1 > r0) v1 = -1e30f;
                    if (cc > r1)     v2 = -1e30f;
                    if (cc + 1 > r1) v3 = -1e30f;
                }
                s[mi][nt][0] = v0; s[mi][nt][1] = v1;
                s[mi][nt][2] = v2; s[mi][nt][3] = v3;
                mx0 = fmaxf(mx0, fmaxf(v0, v1));
                mx1 = fmaxf(mx1, fmaxf(v2, v3));
            }
            mx0 = fmaxf(mx0, __shfl_xor_sync(0xffffffffu, mx0, 1));
            mx0 = fmaxf(mx0, __shfl_xor_sync(0xffffffffu, mx0, 2));
            mx1 = fmaxf(mx1, __shfl_xor_sync(0xffffffffu, mx1, 1));
            mx1 = fmaxf(mx1, __shfl_xor_sync(0xffffffffu, mx1, 2));

            float mn0 = fmaxf(m_i[mi][0], mx0), mn1 = fmaxf(m_i[mi][1], mx1);
            float al0 = exp2f(m_i[mi][0] - mn0), al1 = exp2f(m_i[mi][1] - mn1);
            float ps0 = 0.0f, ps1 = 0.0f;
            const int pr0 = (wr + mi * 16 + g) * QST;
            const int pr1 = pr0 + 8 * QST;
#pragma unroll
            for (int nt = 0; nt < 8; nt++) {
                float p0 = exp2f(s[mi][nt][0] - mn0);
                float p1 = exp2f(s[mi][nt][1] - mn0);
                float p2 = exp2f(s[mi][nt][2] - mn1);
                float p3 = exp2f(s[mi][nt][3] - mn1);
                ps0 += p0 + p1; ps1 += p2 + p3;
                int cg = nt * 8;
                Ps[pr0 + cg + pa0] = __uint_as_float(f2tf32(p0));
                Ps[pr0 + cg + pa1] = __uint_as_float(f2tf32(p1));
                Ps[pr1 + cg + pa0] = __uint_as_float(f2tf32(p2));
                Ps[pr1 + cg + pa1] = __uint_as_float(f2tf32(p3));
                o[mi][nt][0] *= al0; o[mi][nt][1] *= al0;
                o[mi][nt][2] *= al1; o[mi][nt][3] *= al1;
            }
            ps0 += __shfl_xor_sync(0xffffffffu, ps0, 1);
            ps0 += __shfl_xor_sync(0xffffffffu, ps0, 2);
            ps1 += __shfl_xor_sync(0xffffffffu, ps1, 1);
            ps1 += __shfl_xor_sync(0xffffffffu, ps1, 2);
            l_i[mi][0] = l_i[mi][0] * al0 + ps0;
            l_i[mi][1] = l_i[mi][1] * al1 + ps1;
            m_i[mi][0] = mn0; m_i[mi][1] = mn1;
        }
        __syncwarp();

        // ---- O += P V ----
        const uint32_t* Pv = reinterpret_cast<const uint32_t*>(Ps);
#pragma unroll
        for (int kc = 0; kc < 8; kc++) {
            const int kk = kc * 8;
            uint32_t a[2][4];
#pragma unroll
            for (int mi = 0; mi < 2; mi++) {
                const int base = wr + mi * 16;
                uint2 t0 = *reinterpret_cast<const uint2*>(&Pv[(base + g) * QST + kk + 2 * tg]);
                uint2 t1 = *reinterpret_cast<const uint2*>(&Pv[(base + g + 8) * QST + kk + 2 * tg]);
                a[mi][0] = t0.x; a[mi][2] = t0.y;
                a[mi][1] = t1.x; a[mi][3] = t1.y;
            }
#pragma unroll
            for (int nt = 0; nt < 8; nt++) {
                uint32_t b[2];
                b[0] = Vs[(kk + 2 * tg) * KSTV + nt * 8 + g];
                b[1] = Vs[(kk + 2 * tg + 1) * KSTV + nt * 8 + g];
                mma_tf32(o[0][nt], a[0], b);
                mma_tf32(o[1][nt], a[1], b);
            }
        }
        __syncthreads();
    }

    // ---- epilogue: normalize, round, write g_O permuted along EMB ----
#pragma unroll
    for (int mi = 0; mi < 2; mi++) {
        const float inv0 = 1.0f / l_i[mi][0];
        const float inv1 = 1.0f / l_i[mi][1];
        const size_t row0 = (size_t)(q0 + wr + mi * 16 + g) * ROWQ;
        const size_t row1 = row0 + 8 * ROWQ;
#pragma unroll
        for (int nt = 0; nt < 8; nt++) {
            int cg = nt * 8;
            Op[row0 + cg + pa0] = rtf(o[mi][nt][0] * inv0);
            Op[row0 + cg + pa1] = rtf(o[mi][nt][1] * inv0);
            Op[row1 + cg + pa0] = rtf(o[mi][nt][2] * inv1);
            Op[row1 + cg + pa1] = rtf(o[mi][nt][3] * inv1);
        }
    }
}

// ================= launch =====================================================
extern "C" void kernel_launch(void* const* d_in, const int* in_sizes, int n_in,
                              void* d_out, int out_size)
{
    const float* x  = (const float*)d_in[0];
    const float* Wq = (const float*)d_in[1];
    const float* Wk = (const float*)d_in[2];
    const float* Wv = (const float*)d_in[3];
    const float* Wo = (const float*)d_in[4];
    float* out = (float*)d_out;

    cudaFuncSetAttribute(flash_mma, cudaFuncAttributeMaxDynamicSharedMemorySize, FA_SMEM);
    cudaFuncSetAttribute(qkv_mma,   cudaFuncAttributeMaxDynamicSharedMemorySize, GEMM_SMEM);
    cudaFuncSetAttribute(oproj_mma, cudaFuncAttributeMaxDynamicSharedMemorySize, GEMM_SMEM);

    round_x<<<MROWS * EMB / (512 * 8), 512>>>(x);
    transpose_all<<<dim3(80, 32), dim3(32, 32)>>>(Wq, Wk, Wv, Wo);

    qkv_mma<<<dim3(12, 32), 128, GEMM_SMEM>>>();
    flash_mma<<<dim3(32, 16), 128, FA_SMEM>>>();
    oproj_mma<<<dim3(8, 32), 128, GEMM_SMEM>>>(out);
}

// round 7
// speedup vs baseline: 1.0762x; 1.0762x over previous
#include <cuda_runtime.h>
#include <cstdint>
#include <math.h>

#define S_LEN  2048
#define G_GRP  2
#define EMB    1024
#define NH     16
#define NKV    4
#define HD     64
#define MROWS  (S_LEN * G_GRP)      // 4096
#define KVW    (NKV * HD)           // 256
#define ROWQ   (G_GRP * EMB)        // 2048
#define ROWK   (G_GRP * KVW)        // 512

// ---------------- scratch (plain layouts, no permutation) ----------------
__device__ float g_X[MROWS * EMB];
__device__ float g_Q[MROWS * EMB];
__device__ float g_K[MROWS * KVW];
__device__ float g_VT[G_GRP * NKV * HD * S_LEN];   // [(grp*4+kvh)*64 + d][seq]
__device__ float g_O[MROWS * EMB];
__device__ float g_WT[(EMB + 2 * KVW) * EMB];
__device__ float g_WoT[EMB * EMB];

// ================= helpers =================
__device__ __forceinline__ uint32_t smem_u32(const void* p) {
    uint32_t a;
    asm("{ .reg .u64 t; cvta.to.shared.u64 t, %1; cvt.u32.u64 %0, t; }" : "=r"(a) : "l"(p));
    return a;
}
__device__ __forceinline__ uint32_t f2tf32(float x) {
    uint32_t r;
    asm("cvt.rna.tf32.f32 %0, %1;" : "=r"(r) : "f"(x));
    return r;
}
__device__ __forceinline__ float rtf(float x) { return __uint_as_float(f2tf32(x)); }

__device__ __forceinline__ void mma_tf32(float c[4], const uint32_t a[4], const uint32_t b[2]) {
    asm volatile(
        "mma.sync.aligned.m16n8k8.row.col.f32.tf32.tf32.f32 "
        "{%0,%1,%2,%3}, {%4,%5,%6,%7}, {%8,%9}, {%0,%1,%2,%3};"
        : "+f"(c[0]), "+f"(c[1]), "+f"(c[2]), "+f"(c[3])
        : "r"(a[0]), "r"(a[1]), "r"(a[2]), "r"(a[3]), "r"(b[0]), "r"(b[1]));
}

__device__ __forceinline__ void ldsm_x4(uint32_t r[4], uint32_t addr) {
    asm volatile("ldmatrix.sync.aligned.m8n8.x4.shared.b16 {%0,%1,%2,%3}, [%4];"
        : "=r"(r[0]), "=r"(r[1]), "=r"(r[2]), "=r"(r[3]) : "r"(addr));
}

// lane-relative element offsets (in floats) for LDSM source rows
// A-type fragment (16 rows x 8 k): row = (l&7) + ((l>>3)&1)*8, col = (l>>4)*4
__device__ __forceinline__ int ldsmA_off(int lane, int stride) {
    return ((lane & 7) + ((lane >> 3) & 1) * 8) * stride + (lane >> 4) * 4;
}
// B-type fragment (2 n-groups x 8 k): row = (l&7) + ((l>>4)&1)*8, col = ((l>>3)&1)*4
__device__ __forceinline__ int ldsmB_off(int lane, int stride) {
    return ((lane & 7) + ((lane >> 4) & 1) * 8) * stride + ((lane >> 3) & 1) * 4;
}

__device__ __forceinline__ void cpa16(uint32_t dst, const float* src) {
    asm volatile("cp.async.cg.shared.global [%0], [%1], 16;" :: "r"(dst), "l"(src));
}
__device__ __forceinline__ void cpa_commit() { asm volatile("cp.async.commit_group;"); }
template <int N>
__device__ __forceinline__ void cpa_wait() { asm volatile("cp.async.wait_group %0;" :: "n"(N)); }

// ================= producer-side prep =================
__global__ __launch_bounds__(1024) void transpose_all(
    const float* __restrict__ Wq, const float* __restrict__ Wk,
    const float* __restrict__ Wv, const float* __restrict__ Wo)
{
    __shared__ float t[32][33];
    const int bx = blockIdx.x;
    const float* W; float* WT; int N; int nb;
    if (bx < 32)      { W = Wq; WT = g_WT;                               N = EMB; nb = bx; }
    else if (bx < 40) { W = Wk; WT = g_WT + (size_t)EMB * EMB;           N = KVW; nb = bx - 32; }
    else if (bx < 48) { W = Wv; WT = g_WT + (size_t)(EMB + KVW) * EMB;   N = KVW; nb = bx - 40; }
    else              { W = Wo; WT = g_WoT;                              N = EMB; nb = bx - 48; }

    int n = nb * 32 + threadIdx.x;
    int k = blockIdx.y * 32 + threadIdx.y;
    t[threadIdx.y][threadIdx.x] = rtf(W[(size_t)k * N + n]);
    __syncthreads();
    int n2 = nb * 32 + threadIdx.y;
    int k2 = blockIdx.y * 32 + threadIdx.x;
    WT[(size_t)n2 * EMB + k2] = t[threadIdx.x][threadIdx.y];
}

__global__ __launch_bounds__(512) void round_x(const float* __restrict__ x) {
    int i = blockIdx.x * 512 + threadIdx.x;
    float4 v = reinterpret_cast<const float4*>(x)[i];
    reinterpret_cast<float4*>(g_X)[i] = make_float4(rtf(v.x), rtf(v.y), rtf(v.z), rtf(v.w));
}

// ================= tf32 mma GEMM: 128x128 CTA, 64x64 warp tile, LDSM ========
#define AST 36
#define ABUF (128 * AST)
#define GEMM_SMEM (4 * ABUF * 4)     // 73728 B

// OM: 0 = plain write, 1 = tf32-rounded write, 2 = V-transposed rounded write
template <int OM>
__device__ __forceinline__ void gemm_tile(
    const float* __restrict__ A, const float* __restrict__ BT,
    float* __restrict__ C, int ldc, int m0, int n0bt, int c0)
{
    extern __shared__ uint32_t dsm[];
    const uint32_t sb = smem_u32(dsm);

    const int tid  = threadIdx.x;      // 0..127
    const int lane = tid & 31;
    const int wid  = tid >> 5;
    const int wm   = wid >> 1;
    const int wn   = wid & 1;
    const int g    = lane >> 2;
    const int tg   = lane & 3;

    float acc[4][8][4];
#pragma unroll
    for (int mi = 0; mi < 4; mi++)
#pragma unroll
        for (int nt = 0; nt < 8; nt++)
#pragma unroll
            for (int j = 0; j < 4; j++) acc[mi][nt][j] = 0.0f;

    const int row = tid >> 3;
    const int q   = (tid & 7) * 4;

    auto stage = [&](int c, int buf) {
        const int k0 = c * 32;
        const uint32_t aBase = sb + (uint32_t)(2 * buf) * ABUF * 4;
        const uint32_t bBase = aBase + ABUF * 4;
#pragma unroll
        for (int t = 0; t < 8; t++) {
            int r = row + t * 16;
            cpa16(aBase + (uint32_t)(r * AST + q) * 4, &A [(size_t)(m0 + r) * EMB + k0 + q]);
            cpa16(bBase + (uint32_t)(r * AST + q) * 4, &BT[(size_t)(n0bt + r) * EMB + k0 + q]);
        }
    };

    // lane-dependent LDSM base addresses (bytes, relative to buffer base)
    uint32_t aOff[4], bOff[4];
    {
        const int la = ldsmA_off(lane, AST);
        const int lb = ldsmB_off(lane, AST);
#pragma unroll
        for (int mi = 0; mi < 4; mi++)
            aOff[mi] = (uint32_t)(((wm * 64 + mi * 16) * AST + la) * 4);
#pragma unroll
        for (int pr = 0; pr < 4; pr++)
            bOff[pr] = (uint32_t)(((wn * 64 + pr * 16) * AST + lb) * 4);
    }

    stage(0, 0);
    cpa_commit();

    for (int c = 0; c < 32; c++) {
        if (c < 31) {
            stage(c + 1, (c + 1) & 1);
            cpa_commit();
            cpa_wait<1>();
        } else {
            cpa_wait<0>();
        }
        __syncthreads();

        const uint32_t aBase = sb + (uint32_t)(2 * (c & 1)) * ABUF * 4;
        const uint32_t bBase = aBase + ABUF * 4;
#pragma unroll
        for (int kc = 0; kc < 4; kc++) {
            const uint32_t kkB = kc * 32;   // 8 floats
            uint32_t a[4][4];
#pragma unroll
            for (int mi = 0; mi < 4; mi++)
                ldsm_x4(a[mi], aBase + aOff[mi] + kkB);
#pragma unroll
            for (int pr = 0; pr < 4; pr++) {
                uint32_t bfr[4];
                ldsm_x4(bfr, bBase + bOff[pr] + kkB);
#pragma unroll
                for (int mi = 0; mi < 4; mi++) {
                    mma_tf32(acc[mi][pr * 2],     a[mi], bfr);
                    mma_tf32(acc[mi][pr * 2 + 1], a[mi], bfr + 2);
                }
            }
        }
        __syncthreads();
    }

    // epilogue
#pragma unroll
    for (int mi = 0; mi < 4; mi++) {
        int r0 = m0 + wm * 64 + mi * 16 + g;
#pragma unroll
        for (int nt = 0; nt < 8; nt++) {
            int col = c0 + wn * 64 + nt * 8 + 2 * tg;
            if (OM == 2) {
                // write V transposed: g_VT[((m&1)*4 + col>>6)*64 + (col&63)][m>>1]
#pragma unroll
                for (int e = 0; e < 4; e++) {
                    int m = r0 + (e >> 1) * 8;
                    int cc = col + (e & 1);
                    size_t vrow = (size_t)(((m & 1) * 4 + (cc >> 6)) * 64 + (cc & 63));
                    g_VT[vrow * S_LEN + (m >> 1)] = rtf(acc[mi][nt][e]);
                }
            } else if (OM == 1) {
                *reinterpret_cast<float2*>(&C[(size_t)r0 * ldc + col]) =
                    make_float2(rtf(acc[mi][nt][0]), rtf(acc[mi][nt][1]));
                *reinterpret_cast<float2*>(&C[(size_t)(r0 + 8) * ldc + col]) =
                    make_float2(rtf(acc[mi][nt][2]), rtf(acc[mi][nt][3]));
            } else {
                *reinterpret_cast<float2*>(&C[(size_t)r0 * ldc + col]) =
                    make_float2(acc[mi][nt][0], acc[mi][nt][1]);
                *reinterpret_cast<float2*>(&C[(size_t)(r0 + 8) * ldc + col]) =
                    make_float2(acc[mi][nt][2], acc[mi][nt][3]);
            }
        }
    }
}

__global__ __launch_bounds__(128) void qkv_mma() {
    int nb = blockIdx.x;
    int m0 = blockIdx.y * 128;
    if (nb < 8)
        gemm_tile<1>(g_X, g_WT, g_Q, EMB, m0, nb * 128, nb * 128);
    else if (nb < 10)
        gemm_tile<1>(g_X, g_WT, g_K, KVW, m0, nb * 128, (nb - 8) * 128);
    else
        gemm_tile<2>(g_X, g_WT, nullptr, 0, m0, nb * 128, (nb - 10) * 128);
}

__global__ __launch_bounds__(128) void oproj_mma(float* __restrict__ out) {
    gemm_tile<0>(g_O, g_WoT, out, EMB, blockIdx.y * 128, blockIdx.x * 128, blockIdx.x * 128);
}

// ================= flash attention: BM=128, LDSM fragments ===================
#define FST  68                       // common stride (68 % 32 == 4)
#define PS_SZ (128 * FST)             // 8704 floats
#define TBUF  (64 * FST)              // 4352 floats (K or VT tile)
#define FA_SMEM ((PS_SZ + 4 * TBUF) * 4)   // 104448 B

__global__ __launch_bounds__(128) void flash_mma()
{
    extern __shared__ float fsm[];
    float* Ps = fsm;                  // [128][FST]: Q staging, then P
    const uint32_t sb   = smem_u32(fsm);
    const uint32_t sbK0 = sb + PS_SZ * 4;
    const uint32_t sbV0 = sbK0 + 2 * TBUF * 4;

    const int tid  = threadIdx.x;
    const int lane = tid & 31;
    const int w    = tid >> 5;
    const int g    = lane >> 2;
    const int tg   = lane & 3;
    const int wr   = w * 32;

    const int gh  = blockIdx.x;
    const int qb  = (int)gridDim.y - 1 - blockIdx.y;
    const int grp = gh & 1;
    const int h   = gh >> 1;
    const int kvh = h >> 2;

    const float* Qp  = g_Q + grp * EMB + h * HD;
    const float* Kp  = g_K + grp * KVW + kvh * HD;
    const float* VTp = g_VT + (size_t)((grp * 4 + kvh) * 64) * S_LEN;
    float*       Op  = g_O + grp * EMB + h * HD;

    const int q0 = qb * 128;
    const float SC = 0.125f * 1.4426950408889634f;   // (1/sqrt(64)) * log2(e)

    // ---- stage Q * SC (tf32-rounded) into Ps ----
    {
        const int row = tid >> 4;
        const int c   = (tid & 15) * 4;
#pragma unroll
        for (int p = 0; p < 16; p++) {
            int r = row + p * 8;
            float4 qv = *reinterpret_cast<const float4*>(&Qp[(size_t)(q0 + r) * ROWQ + c]);
            float* d = &Ps[r * FST + c];
            d[0] = rtf(qv.x * SC); d[1] = rtf(qv.y * SC);
            d[2] = rtf(qv.z * SC); d[3] = rtf(qv.w * SC);
        }
    }
    __syncthreads();

    // ---- LDSM lane offsets ----
    const int laA = ldsmA_off(lane, FST);
    const int laB = ldsmB_off(lane, FST);
    uint32_t pOff[2];                 // P/Q A-fragment bases (bytes, rel. Ps)
    pOff[0] = (uint32_t)(((wr) * FST + laA) * 4);
    pOff[1] = (uint32_t)(((wr + 16) * FST + laA) * 4);
    uint32_t bOff[4];                 // B-fragment bases for K / VT tiles
#pragma unroll
    for (int pr = 0; pr < 4; pr++)
        bOff[pr] = (uint32_t)((pr * 16 * FST + laB) * 4);

    // ---- hoist Q fragments via LDSM ----
    uint32_t aq[2][8][4];
#pragma unroll
    for (int mi = 0; mi < 2; mi++)
#pragma unroll
        for (int kc = 0; kc < 8; kc++)
            ldsm_x4(aq[mi][kc], sb + pOff[mi] + kc * 32);
    __syncthreads();   // Ps now free for P

    // ---- K/VT staging ----
    const int srow = tid >> 4;                 // 0..7
    const int sq   = (tid & 15) * 4;
    auto stage_kv = [&](int kb, int buf) {
        const int kn = kb * 64;
        const uint32_t kBase = sbK0 + (uint32_t)buf * TBUF * 4;
        const uint32_t vBase = sbV0 + (uint32_t)buf * TBUF * 4;
#pragma unroll
        for (int p = 0; p < 8; p++) {
            int r = srow + p * 8;
            cpa16(kBase + (uint32_t)(r * FST + sq) * 4, &Kp[(size_t)(kn + r) * ROWK + sq]);
            cpa16(vBase + (uint32_t)(r * FST + sq) * 4, &VTp[(size_t)r * S_LEN + kn + sq]);
        }
    };

    float m_i[2][2] = {{-1e30f, -1e30f}, {-1e30f, -1e30f}};
    float l_i[2][2] = {{0.0f, 0.0f}, {0.0f, 0.0f}};
    float o[2][8][4];
#pragma unroll
    for (int mi = 0; mi < 2; mi++)
#pragma unroll
        for (int nt = 0; nt < 8; nt++)
#pragma unroll
            for (int j = 0; j < 4; j++) o[mi][nt][j] = 0.0f;

    const int kbmax = 2 * qb + 1;
    stage_kv(0, 0);
    cpa_commit();

    for (int kb = 0; kb <= kbmax; kb++) {
        const int kn  = kb * 64;
        const int buf = kb & 1;
        if (kb < kbmax) {
            stage_kv(kb + 1, buf ^ 1);
            cpa_commit();
            cpa_wait<1>();
        } else {
            cpa_wait<0>();
        }
        __syncthreads();

        const uint32_t kBase = sbK0 + (uint32_t)buf * TBUF * 4;
        const uint32_t vBase = sbV0 + (uint32_t)buf * TBUF * 4;

        // ---- S = (Q*SC) K^T ----
        float s[2][8][4];
#pragma unroll
        for (int mi = 0; mi < 2; mi++)
#pragma unroll
            for (int nt = 0; nt < 8; nt++)
#pragma unroll
                for (int j = 0; j < 4; j++) s[mi][nt][j] = 0.0f;

#pragma unroll
        for (int kc = 0; kc < 8; kc++) {
            const uint32_t kkB = kc * 32;
#pragma unroll
            for (int pr = 0; pr < 4; pr++) {
                uint32_t bfr[4];
                ldsm_x4(bfr, kBase + bOff[pr] + kkB);
                mma_tf32(s[0][pr * 2],     aq[0][kc], bfr);
                mma_tf32(s[1][pr * 2],     aq[1][kc], bfr);
                mma_tf32(s[0][pr * 2 + 1], aq[0][kc], bfr + 2);
                mma_tf32(s[1][pr * 2 + 1], aq[1][kc], bfr + 2);
            }
        }

        // ---- online softmax (base-2 domain) ----
        const bool diag = (kn + 63 > q0);
#pragma unroll
        for (int mi = 0; mi < 2; mi++) {
            const int r0 = q0 + wr + mi * 16 + g;
            const int r1 = r0 + 8;
            float mx0 = -1e30f, mx1 = -1e30f;
#pragma unroll
            for (int nt = 0; nt < 8; nt++) {
                int cc = kn + nt * 8 + 2 * tg;
                float v0 = s[mi][nt][0], v1 = s[mi][nt][1];
                float v2 = s[mi][nt][2], v3 = s[mi][nt][3];
                if (diag) {
                    if (cc > r0)     v0 = -1e30f;
                    if (cc + 1 > r0) v1 = -1e30f;
                    if (cc > r1)     v2 = -1e30f;
                    if (cc + 1 > r1) v3 = -1e30f;
                }
                s[mi][nt][0] = v0; s[mi][nt][1] = v1;
                s[mi][nt][2] = v2; s[mi][nt][3] = v3;
                mx0 = fmaxf(mx0, fmaxf(v0, v1));
                mx1 = fmaxf(mx1, fmaxf(v2, v3));
            }
            mx0 = fmaxf(mx0, __shfl_xor_sync(0xffffffffu, mx0, 1));
            mx0 = fmaxf(mx0, __shfl_xor_sync(0xffffffffu, mx0, 2));
            mx1 = fmaxf(mx1, __shfl_xor_sync(0xffffffffu, mx1, 1));
            mx1 = fmaxf(mx1, __shfl_xor_sync(0xffffffffu, mx1, 2));

            float mn0 = fmaxf(m_i[mi][0], mx0), mn1 = fmaxf(m_i[mi][1], mx1);
            float al0 = exp2f(m_i[mi][0] - mn0), al1 = exp2f(m_i[mi][1] - mn1);
            float ps0 = 0.0f, ps1 = 0.0f;
            const int pr0 = (wr + mi * 16 + g) * FST;
            const int pr1 = pr0 + 8 * FST;
#pragma unroll
            for (int nt = 0; nt < 8; nt++) {
                float p0 = exp2f(s[mi][nt][0] - mn0);
                float p1 = exp2f(s[mi][nt][1] - mn0);
                float p2 = exp2f(s[mi][nt][2] - mn1);
                float p3 = exp2f(s[mi][nt][3] - mn1);
                ps0 += p0 + p1; ps1 += p2 + p3;
                int cc = nt * 8 + 2 * tg;
                Ps[pr0 + cc]     = __uint_as_float(f2tf32(p0));
                Ps[pr0 + cc + 1] = __uint_as_float(f2tf32(p1));
                Ps[pr1 + cc]     = __uint_as_float(f2tf32(p2));
                Ps[pr1 + cc + 1] = __uint_as_float(f2tf32(p3));
                o[mi][nt][0] *= al0; o[mi][nt][1] *= al0;
                o[mi][nt][2] *= al1; o[mi][nt][3] *= al1;
            }
            ps0 += __shfl_xor_sync(0xffffffffu, ps0, 1);
            ps0 += __shfl_xor_sync(0xffffffffu, ps0, 2);
            ps1 += __shfl_xor_sync(0xffffffffu, ps1, 1);
            ps1 += __shfl_xor_sync(0xffffffffu, ps1, 2);
            l_i[mi][0] = l_i[mi][0] * al0 + ps0;
            l_i[mi][1] = l_i[mi][1] * al1 + ps1;
            m_i[mi][0] = mn0; m_i[mi][1] = mn1;
        }
        __syncwarp();

        // ---- O += P V  (P via LDSM from Ps; V via LDSM from transposed tile) ----
#pragma unroll
        for (int kc = 0; kc < 8; kc++) {
            const uint32_t kkB = kc * 32;
            uint32_t a0[4], a1[4];
            ldsm_x4(a0, sb + pOff[0] + kkB);
            ldsm_x4(a1, sb + pOff[1] + kkB);
#pragma unroll
            for (int pr = 0; pr < 4; pr++) {
                uint32_t bfr[4];
                ldsm_x4(bfr, vBase + bOff[pr] + kkB);
                mma_tf32(o[0][pr * 2],     a0, bfr);
                mma_tf32(o[1][pr * 2],     a1, bfr);
                mma_tf32(o[0][pr * 2 + 1], a0, bfr + 2);
                mma_tf32(o[1][pr * 2 + 1], a1, bfr + 2);
            }
        }
        __syncthreads();
    }

    // ---- epilogue: normalize, round, write g_O ----
#pragma unroll
    for (int mi = 0; mi < 2; mi++) {
        const float inv0 = 1.0f / l_i[mi][0];
        const float inv1 = 1.0f / l_i[mi][1];
        const size_t row0 = (size_t)(q0 + wr + mi * 16 + g) * ROWQ;
        const size_t row1 = row0 + 8 * ROWQ;
#pragma unroll
        for (int nt = 0; nt < 8; nt++) {
            int cc = nt * 8 + 2 * tg;
            *reinterpret_cast<float2*>(&Op[row0 + cc]) =
                make_float2(rtf(o[mi][nt][0] * inv0), rtf(o[mi][nt][1] * inv0));
            *reinterpret_cast<float2*>(&Op[row1 + cc]) =
                make_float2(rtf(o[mi][nt][2] * inv1), rtf(o[mi][nt][3] * inv1));
        }
    }
}

// ================= launch =====================================================
extern "C" void kernel_launch(void* const* d_in, const int* in_sizes, int n_in,
                              void* d_out, int out_size)
{
    const float* x  = (const float*)d_in[0];
    const float* Wq = (const float*)d_in[1];
    const float* Wk = (const float*)d_in[2];
    const float* Wv = (const float*)d_in[3];
    const float* Wo = (const float*)d_in[4];
    float* out = (float*)d_out;

    cudaFuncSetAttribute(flash_mma, cudaFuncAttributeMaxDynamicSharedMemorySize, FA_SMEM);
    cudaFuncSetAttribute(qkv_mma,   cudaFuncAttributeMaxDynamicSharedMemorySize, GEMM_SMEM);
    cudaFuncSetAttribute(oproj_mma, cudaFuncAttributeMaxDynamicSharedMemorySize, GEMM_SMEM);

    round_x<<<MROWS * EMB / (512 * 4), 512>>>(x);
    transpose_all<<<dim3(80, 32), dim3(32, 32)>>>(Wq, Wk, Wv, Wo);

    qkv_mma<<<dim3(12, 32), 128, GEMM_SMEM>>>();
    flash_mma<<<dim3(32, 16), 128, FA_SMEM>>>();
    oproj_mma<<<dim3(8, 32), 128, GEMM_SMEM>>>(out);
}

// round 8
// speedup vs baseline: 1.1850x; 1.1011x over previous
#include <cuda_runtime.h>
#include <cstdint>
#include <math.h>

#define S_LEN  2048
#define G_GRP  2
#define EMB    1024
#define NH     16
#define NKV    4
#define HD     64
#define MROWS  (S_LEN * G_GRP)      // 4096
#define KVW    (NKV * HD)           // 256
#define ROWQ   (G_GRP * EMB)        // 2048
#define ROWK   (G_GRP * KVW)        // 512

// ---------------- scratch ----------------
__device__ float g_X[MROWS * EMB];
__device__ float g_Q[MROWS * EMB];
__device__ float g_K[MROWS * KVW];
__device__ float g_V[MROWS * KVW];                 // natural [m][kvh*64+d]
__device__ float g_VT[G_GRP * NKV * HD * S_LEN];   // [(grp*4+kvh)*64 + d][seq]
__device__ float g_O[MROWS * EMB];
__device__ float g_WT[(EMB + 2 * KVW) * EMB];
__device__ float g_WoT[EMB * EMB];

// ================= helpers =================
__device__ __forceinline__ uint32_t smem_u32(const void* p) {
    uint32_t a;
    asm("{ .reg .u64 t; cvta.to.shared.u64 t, %1; cvt.u32.u64 %0, t; }" : "=r"(a) : "l"(p));
    return a;
}
__device__ __forceinline__ uint32_t f2tf32(float x) {
    uint32_t r;
    asm("cvt.rna.tf32.f32 %0, %1;" : "=r"(r) : "f"(x));
    return r;
}
__device__ __forceinline__ float rtf(float x) { return __uint_as_float(f2tf32(x)); }

__device__ __forceinline__ void mma_tf32(float c[4], const uint32_t a[4], const uint32_t b[2]) {
    asm volatile(
        "mma.sync.aligned.m16n8k8.row.col.f32.tf32.tf32.f32 "
        "{%0,%1,%2,%3}, {%4,%5,%6,%7}, {%8,%9}, {%0,%1,%2,%3};"
        : "+f"(c[0]), "+f"(c[1]), "+f"(c[2]), "+f"(c[3])
        : "r"(a[0]), "r"(a[1]), "r"(a[2]), "r"(a[3]), "r"(b[0]), "r"(b[1]));
}

__device__ __forceinline__ void ldsm_x4(uint32_t r[4], uint32_t addr) {
    asm volatile("ldmatrix.sync.aligned.m8n8.x4.shared.b16 {%0,%1,%2,%3}, [%4];"
        : "=r"(r[0]), "=r"(r[1]), "=r"(r[2]), "=r"(r[3]) : "r"(addr));
}
__device__ __forceinline__ int ldsmA_off(int lane, int stride) {
    return ((lane & 7) + ((lane >> 3) & 1) * 8) * stride + (lane >> 4) * 4;
}
__device__ __forceinline__ int ldsmB_off(int lane, int stride) {
    return ((lane & 7) + ((lane >> 4) & 1) * 8) * stride + ((lane >> 3) & 1) * 4;
}

__device__ __forceinline__ void cpa16(uint32_t dst, const float* src) {
    asm volatile("cp.async.cg.shared.global [%0], [%1], 16;" :: "r"(dst), "l"(src));
}
__device__ __forceinline__ void cpa_commit() { asm volatile("cp.async.commit_group;"); }
template <int N>
__device__ __forceinline__ void cpa_wait() { asm volatile("cp.async.wait_group %0;" :: "n"(N)); }

// ================= producer-side prep =================
__global__ __launch_bounds__(1024) void transpose_all(
    const float* __restrict__ Wq, const float* __restrict__ Wk,
    const float* __restrict__ Wv, const float* __restrict__ Wo)
{
    __shared__ float t[32][33];
    const int bx = blockIdx.x;
    const float* W; float* WT; int N; int nb;
    if (bx < 32)      { W = Wq; WT = g_WT;                               N = EMB; nb = bx; }
    else if (bx < 40) { W = Wk; WT = g_WT + (size_t)EMB * EMB;           N = KVW; nb = bx - 32; }
    else if (bx < 48) { W = Wv; WT = g_WT + (size_t)(EMB + KVW) * EMB;   N = KVW; nb = bx - 40; }
    else              { W = Wo; WT = g_WoT;                              N = EMB; nb = bx - 48; }

    int n = nb * 32 + threadIdx.x;
    int k = blockIdx.y * 32 + threadIdx.y;
    t[threadIdx.y][threadIdx.x] = rtf(W[(size_t)k * N + n]);
    __syncthreads();
    int n2 = nb * 32 + threadIdx.y;
    int k2 = blockIdx.y * 32 + threadIdx.x;
    WT[(size_t)n2 * EMB + k2] = t[threadIdx.x][threadIdx.y];
}

__global__ __launch_bounds__(512) void round_x(const float* __restrict__ x) {
    int i = blockIdx.x * 512 + threadIdx.x;
    float4 v = reinterpret_cast<const float4*>(x)[i];
    reinterpret_cast<float4*>(g_X)[i] = make_float4(rtf(v.x), rtf(v.y), rtf(v.z), rtf(v.w));
}

// coalesced V transpose: g_V[m][c] -> g_VT[(m&1)*256 + c][m>>1]
__global__ __launch_bounds__(256) void transpose_v() {
    __shared__ float t[64][33];
    const int mt = blockIdx.x;          // 0..63
    const int ct = blockIdx.y;          // 0..7
    const int tx = threadIdx.x & 31;
    const int ty = threadIdx.x >> 5;    // 0..7
#pragma unroll
    for (int k = 0; k < 8; k++) {
        int ml = ty + k * 8;            // 0..63
        t[ml][tx] = g_V[(size_t)(mt * 64 + ml) * KVW + ct * 32 + tx];
    }
    __syncthreads();
#pragma unroll
    for (int k = 0; k < 8; k++) {
        int rs  = ty + k * 8;           // 0..63
        int grp = rs >> 5, c = rs & 31;
        g_VT[(size_t)(grp * 256 + ct * 32 + c) * S_LEN + mt * 32 + tx] = t[grp + 2 * tx][c];
    }
}

// ================= tf32 mma GEMM: 3-stage cp.async, one sync/chunk ==========
#define AST 36
#define ABUF (128 * AST)
#define GEMM_SMEM (6 * ABUF * 4)     // 110592 B

template <bool ROUND>
__device__ __forceinline__ void gemm_tile(
    const float* __restrict__ A, const float* __restrict__ BT,
    float* __restrict__ C, int ldc, int m0, int n0bt, int c0)
{
    extern __shared__ uint32_t dsm[];
    const uint32_t sb = smem_u32(dsm);

    const int tid  = threadIdx.x;      // 0..127
    const int lane = tid & 31;
    const int wid  = tid >> 5;
    const int wm   = wid >> 1;
    const int wn   = wid & 1;
    const int g    = lane >> 2;
    const int tg   = lane & 3;

    float acc[4][8][4];
#pragma unroll
    for (int mi = 0; mi < 4; mi++)
#pragma unroll
        for (int nt = 0; nt < 8; nt++)
#pragma unroll
            for (int j = 0; j < 4; j++) acc[mi][nt][j] = 0.0f;

    const int row = tid >> 3;
    const int q   = (tid & 7) * 4;

    auto stage = [&](int c, int buf) {
        const int k0 = c * 32;
        const uint32_t aBase = sb + (uint32_t)(2 * buf) * ABUF * 4;
        const uint32_t bBase = aBase + ABUF * 4;
#pragma unroll
        for (int t = 0; t < 8; t++) {
            int r = row + t * 16;
            cpa16(aBase + (uint32_t)(r * AST + q) * 4, &A [(size_t)(m0 + r) * EMB + k0 + q]);
            cpa16(bBase + (uint32_t)(r * AST + q) * 4, &BT[(size_t)(n0bt + r) * EMB + k0 + q]);
        }
    };

    uint32_t aOff[4], bOff[4];
    {
        const int la = ldsmA_off(lane, AST);
        const int lb = ldsmB_off(lane, AST);
#pragma unroll
        for (int mi = 0; mi < 4; mi++)
            aOff[mi] = (uint32_t)(((wm * 64 + mi * 16) * AST + la) * 4);
#pragma unroll
        for (int pr = 0; pr < 4; pr++)
            bOff[pr] = (uint32_t)(((wn * 64 + pr * 16) * AST + lb) * 4);
    }

    stage(0, 0); cpa_commit();
    stage(1, 1); cpa_commit();

    for (int c = 0; c < 32; c++) {
        if (c < 31) cpa_wait<1>(); else cpa_wait<0>();
        __syncthreads();                       // single barrier per chunk
        if (c + 2 < 32) { stage(c + 2, (c + 2) % 3); cpa_commit(); }

        const uint32_t aBase = sb + (uint32_t)(2 * (c % 3)) * ABUF * 4;
        const uint32_t bBase = aBase + ABUF * 4;
#pragma unroll
        for (int kc = 0; kc < 4; kc++) {
            const uint32_t kkB = kc * 32;
            uint32_t a[4][4];
#pragma unroll
            for (int mi = 0; mi < 4; mi++)
                ldsm_x4(a[mi], aBase + aOff[mi] + kkB);
#pragma unroll
            for (int pr = 0; pr < 4; pr++) {
                uint32_t bfr[4];
                ldsm_x4(bfr, bBase + bOff[pr] + kkB);
#pragma unroll
                for (int mi = 0; mi < 4; mi++) {
                    mma_tf32(acc[mi][pr * 2],     a[mi], bfr);
                    mma_tf32(acc[mi][pr * 2 + 1], a[mi], bfr + 2);
                }
            }
        }
    }

#pragma unroll
    for (int mi = 0; mi < 4; mi++) {
        int r0 = m0 + wm * 64 + mi * 16 + g;
#pragma unroll
        for (int nt = 0; nt < 8; nt++) {
            int col = c0 + wn * 64 + nt * 8 + 2 * tg;
            float2 v0, v1;
            if (ROUND) {
                v0 = make_float2(rtf(acc[mi][nt][0]), rtf(acc[mi][nt][1]));
                v1 = make_float2(rtf(acc[mi][nt][2]), rtf(acc[mi][nt][3]));
            } else {
                v0 = make_float2(acc[mi][nt][0], acc[mi][nt][1]);
                v1 = make_float2(acc[mi][nt][2], acc[mi][nt][3]);
            }
            *reinterpret_cast<float2*>(&C[(size_t)r0 * ldc + col])       = v0;
            *reinterpret_cast<float2*>(&C[(size_t)(r0 + 8) * ldc + col]) = v1;
        }
    }
}

__global__ __launch_bounds__(128) void qkv_mma() {
    int nb = blockIdx.x;
    int m0 = blockIdx.y * 128;
    if (nb < 8)
        gemm_tile<true>(g_X, g_WT, g_Q, EMB, m0, nb * 128, nb * 128);
    else if (nb < 10)
        gemm_tile<true>(g_X, g_WT, g_K, KVW, m0, nb * 128, (nb - 8) * 128);
    else
        gemm_tile<true>(g_X, g_WT, g_V, KVW, m0, nb * 128, (nb - 10) * 128);
}

__global__ __launch_bounds__(128) void oproj_mma(float* __restrict__ out) {
    gemm_tile<false>(g_O, g_WoT, out, EMB, blockIdx.y * 128, blockIdx.x * 128, blockIdx.x * 128);
}

// ================= flash attention: BM=128, 8 warps x 16 rows ================
#define FST  68
#define PS_SZ (128 * FST)             // 8704 floats
#define TBUF  (64 * FST)              // 4352 floats
#define FA_SMEM ((PS_SZ + 4 * TBUF) * 4)   // 104448 B

__global__ __launch_bounds__(256, 2) void flash_mma()
{
    extern __shared__ float fsm[];
    float* Ps = fsm;                  // [128][FST]: Q staging, then P
    const uint32_t sb   = smem_u32(fsm);
    const uint32_t sbK0 = sb + PS_SZ * 4;
    const uint32_t sbV0 = sbK0 + 2 * TBUF * 4;

    const int tid  = threadIdx.x;     // 0..255
    const int lane = tid & 31;
    const int w    = tid >> 5;        // 0..7
    const int g    = lane >> 2;
    const int tg   = lane & 3;
    const int wr   = w * 16;          // warp's 16 q-rows

    const int gh  = blockIdx.x;
    const int qb  = (int)gridDim.y - 1 - blockIdx.y;
    const int grp = gh & 1;
    const int h   = gh >> 1;
    const int kvh = h >> 2;

    const float* Qp  = g_Q + grp * EMB + h * HD;
    const float* Kp  = g_K + grp * KVW + kvh * HD;
    const float* VTp = g_VT + (size_t)((grp * 4 + kvh) * 64) * S_LEN;
    float*       Op  = g_O + grp * EMB + h * HD;

    const int q0 = qb * 128;
    const float SC = 0.125f * 1.4426950408889634f;

    // ---- stage Q * SC (tf32-rounded) ----
    {
        const int row = tid >> 4;     // 0..15
        const int c   = (tid & 15) * 4;
#pragma unroll
        for (int p = 0; p < 8; p++) {
            int r = row + p * 16;
            float4 qv = *reinterpret_cast<const float4*>(&Qp[(size_t)(q0 + r) * ROWQ + c]);
            float* d = &Ps[r * FST + c];
            d[0] = rtf(qv.x * SC); d[1] = rtf(qv.y * SC);
            d[2] = rtf(qv.z * SC); d[3] = rtf(qv.w * SC);
        }
    }
    __syncthreads();

    // ---- LDSM lane offsets ----
    const int laA = ldsmA_off(lane, FST);
    const int laB = ldsmB_off(lane, FST);
    const uint32_t pOff = (uint32_t)((wr * FST + laA) * 4);
    uint32_t bOff[4];
#pragma unroll
    for (int pr = 0; pr < 4; pr++)
        bOff[pr] = (uint32_t)((pr * 16 * FST + laB) * 4);

    // ---- hoist Q fragments ----
    uint32_t aq[8][4];
#pragma unroll
    for (int kc = 0; kc < 8; kc++)
        ldsm_x4(aq[kc], sb + pOff + kc * 32);
    __syncthreads();   // Ps now free for P

    // ---- K/VT staging (256 threads) ----
    const int srow = tid >> 4;        // 0..15
    const int sq   = (tid & 15) * 4;
    auto stage_kv = [&](int kb, int buf) {
        const int kn = kb * 64;
        const uint32_t kBase = sbK0 + (uint32_t)buf * TBUF * 4;
        const uint32_t vBase = sbV0 + (uint32_t)buf * TBUF * 4;
#pragma unroll
        for (int p = 0; p < 4; p++) {
            int r = srow + p * 16;
            cpa16(kBase + (uint32_t)(r * FST + sq) * 4, &Kp[(size_t)(kn + r) * ROWK + sq]);
            cpa16(vBase + (uint32_t)(r * FST + sq) * 4, &VTp[(size_t)r * S_LEN + kn + sq]);
        }
    };

    float m_i[2] = {-1e30f, -1e30f};
    float l_i[2] = {0.0f, 0.0f};
    float o[8][4];
#pragma unroll
    for (int nt = 0; nt < 8; nt++)
#pragma unroll
        for (int j = 0; j < 4; j++) o[nt][j] = 0.0f;

    const int kbmax = 2 * qb + 1;
    stage_kv(0, 0);
    cpa_commit();

    for (int kb = 0; kb <= kbmax; kb++) {
        const int kn  = kb * 64;
        const int buf = kb & 1;
        if (kb < kbmax) {
            stage_kv(kb + 1, buf ^ 1);
            cpa_commit();
            cpa_wait<1>();
        } else {
            cpa_wait<0>();
        }
        __syncthreads();

        const uint32_t kBase = sbK0 + (uint32_t)buf * TBUF * 4;
        const uint32_t vBase = sbV0 + (uint32_t)buf * TBUF * 4;

        // ---- S = (Q*SC) K^T ----
        float s[8][4];
#pragma unroll
        for (int nt = 0; nt < 8; nt++)
#pragma unroll
            for (int j = 0; j < 4; j++) s[nt][j] = 0.0f;

#pragma unroll
        for (int kc = 0; kc < 8; kc++) {
            const uint32_t kkB = kc * 32;
#pragma unroll
            for (int pr = 0; pr < 4; pr++) {
                uint32_t bfr[4];
                ldsm_x4(bfr, kBase + bOff[pr] + kkB);
                mma_tf32(s[pr * 2],     aq[kc], bfr);
                mma_tf32(s[pr * 2 + 1], aq[kc], bfr + 2);
            }
        }

        // ---- online softmax ----
        const bool diag = (kn + 63 > q0);
        {
            const int r0 = q0 + wr + g;
            const int r1 = r0 + 8;
            float mx0 = -1e30f, mx1 = -1e30f;
#pragma unroll
            for (int nt = 0; nt < 8; nt++) {
                int cc = kn + nt * 8 + 2 * tg;
                float v0 = s[nt][0], v1 = s[nt][1], v2 = s[nt][2], v3 = s[nt][3];
                if (diag) {
                    if (cc > r0)     v0 = -1e30f;
                    if (cc + 1 > r0) v1 = -1e30f;
                    if (cc > r1)     v2 = -1e30f;
                    if (cc + 1 > r1) v3 = -1e30f;
                }
                s[nt][0] = v0; s[nt][1] = v1; s[nt][2] = v2; s[nt][3] = v3;
                mx0 = fmaxf(mx0, fmaxf(v0, v1));
                mx1 = fmaxf(mx1, fmaxf(v2, v3));
            }
            mx0 = fmaxf(mx0, __shfl_xor_sync(0xffffffffu, mx0, 1));
            mx0 = fmaxf(mx0, __shfl_xor_sync(0xffffffffu, mx0, 2));
            mx1 = fmaxf(mx1, __shfl_xor_sync(0xffffffffu, mx1, 1));
            mx1 = fmaxf(mx1, __shfl_xor_sync(0xffffffffu, mx1, 2));

            float mn0 = fmaxf(m_i[0], mx0), mn1 = fmaxf(m_i[1], mx1);
            float al0 = exp2f(m_i[0] - mn0), al1 = exp2f(m_i[1] - mn1);
            float ps0 = 0.0f, ps1 = 0.0f;
            const int pr0 = (wr + g) * FST;
            const int pr1 = pr0 + 8 * FST;
#pragma unroll
            for (int nt = 0; nt < 8; nt++) {
                float p0 = exp2f(s[nt][0] - mn0);
                float p1 = exp2f(s[nt][1] - mn0);
                float p2 = exp2f(s[nt][2] - mn1);
                float p3 = exp2f(s[nt][3] - mn1);
                ps0 += p0 + p1; ps1 += p2 + p3;
                int cc = nt * 8 + 2 * tg;
                Ps[pr0 + cc]     = __uint_as_float(f2tf32(p0));
                Ps[pr0 + cc + 1] = __uint_as_float(f2tf32(p1));
                Ps[pr1 + cc]     = __uint_as_float(f2tf32(p2));
                Ps[pr1 + cc + 1] = __uint_as_float(f2tf32(p3));
                o[nt][0] *= al0; o[nt][1] *= al0;
                o[nt][2] *= al1; o[nt][3] *= al1;
            }
            ps0 += __shfl_xor_sync(0xffffffffu, ps0, 1);
            ps0 += __shfl_xor_sync(0xffffffffu, ps0, 2);
            ps1 += __shfl_xor_sync(0xffffffffu, ps1, 1);
            ps1 += __shfl_xor_sync(0xffffffffu, ps1, 2);
            l_i[0] = l_i[0] * al0 + ps0;
            l_i[1] = l_i[1] * al1 + ps1;
            m_i[0] = mn0; m_i[1] = mn1;
        }
        __syncwarp();

        // ---- O += P V ----
#pragma unroll
        for (int kc = 0; kc < 8; kc++) {
            const uint32_t kkB = kc * 32;
            uint32_t a[4];
            ldsm_x4(a, sb + pOff + kkB);
#pragma unroll
            for (int pr = 0; pr < 4; pr++) {
                uint32_t bfr[4];
                ldsm_x4(bfr, vBase + bOff[pr] + kkB);
                mma_tf32(o[pr * 2],     a, bfr);
                mma_tf32(o[pr * 2 + 1], a, bfr + 2);
            }
        }
        __syncthreads();
    }

    // ---- epilogue ----
    const float inv0 = 1.0f / l_i[0];
    const float inv1 = 1.0f / l_i[1];
    const size_t row0 = (size_t)(q0 + wr + g) * ROWQ;
    const size_t row1 = row0 + 8 * ROWQ;
#pragma unroll
    for (int nt = 0; nt < 8; nt++) {
        int cc = nt * 8 + 2 * tg;
        *reinterpret_cast<float2*>(&Op[row0 + cc]) =
            make_float2(rtf(o[nt][0] * inv0), rtf(o[nt][1] * inv0));
        *reinterpret_cast<float2*>(&Op[row1 + cc]) =
            make_float2(rtf(o[nt][2] * inv1), rtf(o[nt][3] * inv1));
    }
}

// ================= launch =====================================================
extern "C" void kernel_launch(void* const* d_in, const int* in_sizes, int n_in,
                              void* d_out, int out_size)
{
    const float* x  = (const float*)d_in[0];
    const float* Wq = (const float*)d_in[1];
    const float* Wk = (const float*)d_in[2];
    const float* Wv = (const float*)d_in[3];
    const float* Wo = (const float*)d_in[4];
    float* out = (float*)d_out;

    cudaFuncSetAttribute(flash_mma, cudaFuncAttributeMaxDynamicSharedMemorySize, FA_SMEM);
    cudaFuncSetAttribute(qkv_mma,   cudaFuncAttributeMaxDynamicSharedMemorySize, GEMM_SMEM);
    cudaFuncSetAttribute(oproj_mma, cudaFuncAttributeMaxDynamicSharedMemorySize, GEMM_SMEM);

    round_x<<<MROWS * EMB / (512 * 4), 512>>>(x);
    transpose_all<<<dim3(80, 32), dim3(32, 32)>>>(Wq, Wk, Wv, Wo);

    qkv_mma<<<dim3(12, 32), 128, GEMM_SMEM>>>();
    transpose_v<<<dim3(64, 8), 256>>>();
    flash_mma<<<dim3(32, 16), 256, FA_SMEM>>>();
    oproj_mma<<<dim3(8, 32), 128, GEMM_SMEM>>>(out);
}